// round 16
// baseline (speedup 1.0000x reference)
#include <cuda_runtime.h>
#include <cuda_fp16.h>
#include <math.h>
#include <stdint.h>

#define BB 4
#define NN 1024
#define TT 4096
#define DIM 768
#define HEADS 12
#define HD 64
#define HID 3072
#define NE 8

#define NSTAGE 4
#define HKPAD 40   // gemm smem pitch in halves (80B rows; ldmatrix conflict-free)

#define ASTG 3     // attention K/V stages
#define APITCH 72  // attention pitch in halves

// half weight scratch offsets (in halves)
#define W_QKV_OFF 0
#define W_QKV_N   (3 * DIM * DIM)
#define W_PROJ_OFF (W_QKV_OFF + W_QKV_N)
#define W_PROJ_N  (DIM * DIM)
#define W_W1_OFF  (W_PROJ_OFF + W_PROJ_N)
#define W_W1_N    (NE * HID * DIM)
#define W_W2_OFF  (W_W1_OFF + W_W1_N)
#define W_W2_N    (NE * DIM * HID)
#define W_TOTAL   (W_W2_OFF + W_W2_N)

// ---------------- scratch (static device globals; no allocs) ----------------
__device__ __half g_h[(size_t)TT * DIM];
__device__ __half g_qkv[(size_t)TT * 3 * DIM];
__device__ __half g_attn[(size_t)TT * DIM];
__device__ float  g_x1[(size_t)TT * DIM];
__device__ __half g_h1[(size_t)NE * TT * HID];
__device__ __half g_wh[(size_t)W_TOTAL];
__device__ int    g_cnt[NE];
__device__ int    g_ptok[NE * TT];
__device__ float  g_pw[NE * TT];

__global__ void zero_cnt_kernel(int* c) {
    if (threadIdx.x < NE) c[threadIdx.x] = 0;
}

// ---------------- helpers ------------------------------------------------------
__device__ __forceinline__ uint32_t h2u(__half2 v) {
    union { __half2 h; uint32_t u; } cvt;
    cvt.h = v;
    return cvt.u;
}
__device__ __forceinline__ uint32_t pack2(float a, float b) {
    return h2u(__floats2half2_rn(a, b));
}

__device__ __forceinline__ void mma_f16(float* c, const uint32_t* a, const uint32_t* b) {
    asm volatile(
        "mma.sync.aligned.m16n8k16.row.col.f32.f16.f16.f32 "
        "{%0,%1,%2,%3}, {%4,%5,%6,%7}, {%8,%9}, {%0,%1,%2,%3};"
        : "+f"(c[0]), "+f"(c[1]), "+f"(c[2]), "+f"(c[3])
        : "r"(a[0]), "r"(a[1]), "r"(a[2]), "r"(a[3]), "r"(b[0]), "r"(b[1]));
}

__device__ __forceinline__ void ldsm4(uint32_t* r, uint32_t addr) {
    asm volatile("ldmatrix.sync.aligned.m8n8.x4.shared.b16 {%0,%1,%2,%3}, [%4];"
                 : "=r"(r[0]), "=r"(r[1]), "=r"(r[2]), "=r"(r[3]) : "r"(addr));
}
__device__ __forceinline__ void ldsm4t(uint32_t* r, uint32_t addr) {
    asm volatile("ldmatrix.sync.aligned.m8n8.x4.trans.shared.b16 {%0,%1,%2,%3}, [%4];"
                 : "=r"(r[0]), "=r"(r[1]), "=r"(r[2]), "=r"(r[3]) : "r"(addr));
}

__device__ __forceinline__ void cp16(uint32_t dst, const void* src, int sz) {
    asm volatile("cp.async.cg.shared.global [%0], [%1], 16, %2;"
                 :: "r"(dst), "l"(src), "r"(sz));
}

// ---------------- fused f32 -> f16 conversion of ALL weights -------------------
__global__ void tohalf_all(const float4* __restrict__ qkv_w, const float4* __restrict__ proj_w,
                           const float4* __restrict__ w1, const float4* __restrict__ w2,
                           uint4* __restrict__ dst) {
    const int n8 = W_TOTAL / 8;
    int i = blockIdx.x * blockDim.x + threadIdx.x;
    int stride = gridDim.x * blockDim.x;
    for (; i < n8; i += stride) {
        int e = i * 8;
        const float4* src;
        int off;
        if (e < W_PROJ_OFF)      { src = qkv_w;  off = e - W_QKV_OFF; }
        else if (e < W_W1_OFF)   { src = proj_w; off = e - W_PROJ_OFF; }
        else if (e < W_W2_OFF)   { src = w1;     off = e - W_W1_OFF; }
        else                     { src = w2;     off = e - W_W2_OFF; }
        float4 a = src[off / 4];
        float4 b = src[off / 4 + 1];
        uint4 o;
        o.x = pack2(a.x, a.y); o.y = pack2(a.z, a.w);
        o.z = pack2(b.x, b.y); o.w = pack2(b.z, b.w);
        dst[i] = o;
    }
}

// ---------------- layernorm (fp16 output) --------------------------------------
__global__ void ln_kernel(const float* __restrict__ x, const float* __restrict__ g,
                          const float* __restrict__ b, __half* __restrict__ o) {
    __shared__ float xs[DIM];
    __shared__ float red[256];
    int t = blockIdx.x, tid = threadIdx.x;
    const float* xr = x + (size_t)t * DIM;
    float s = 0.f;
    for (int i = tid; i < DIM; i += 256) { float v = xr[i]; xs[i] = v; s += v; }
    red[tid] = s; __syncthreads();
    for (int st = 128; st > 0; st >>= 1) { if (tid < st) red[tid] += red[tid + st]; __syncthreads(); }
    float mu = red[0] * (1.f / DIM);
    __syncthreads();
    s = 0.f;
    for (int i = tid; i < DIM; i += 256) { float d = xs[i] - mu; s += d * d; }
    red[tid] = s; __syncthreads();
    for (int st = 128; st > 0; st >>= 1) { if (tid < st) red[tid] += red[tid + st]; __syncthreads(); }
    float inv = rsqrtf(red[0] * (1.f / DIM) + 1e-5f);
    __half* orow = o + (size_t)t * DIM;
    for (int i = tid; i < DIM; i += 256)
        orow[i] = __float2half_rn((xs[i] - mu) * inv * g[i] + b[i]);
}

// ---------------- fp16 tensor-core GEMM (R12 geometry, 4-stage) ----------------
// 256 threads, 8 warps of 32x64, BK=32.  OUTMODE: 0 = float, 2 = half, 3 = scatter
template <bool GATHER, bool GELU, int OUTMODE>
__global__ void __launch_bounds__(256, 2)
gemm_hc(const __half* __restrict__ A, const __half* __restrict__ Bw,
        const float* __restrict__ bias, const float* __restrict__ resid,
        void* __restrict__ Cout, int M, int N, int K,
        const int* __restrict__ rows, const int* __restrict__ cnts,
        const float* __restrict__ pw,
        size_t sA, size_t sB, size_t sC) {
    extern __shared__ __half smh[];
    __half* SA = smh;
    __half* SB = smh + (size_t)NSTAGE * 128 * HKPAD;

    int z = blockIdx.z;
    A += (size_t)z * sA; Bw += (size_t)z * sB;
    if (bias) bias += (size_t)z * N;
    if (rows) rows += (size_t)z * TT;
    if (pw)   pw += (size_t)z * TT;
    int Mz = cnts ? cnts[z] : M;
    if (Mz > M) Mz = M;
    int m0 = blockIdx.y * 128;
    if (m0 >= Mz) return;
    int n0 = blockIdx.x * 128;

    int tid = threadIdx.x;
    int r0 = tid >> 2, kq = tid & 3;

    const __half *ga0, *ga1;
    int za0 = 16, za1 = 16;
    if (GATHER) {
        int i0 = m0 + r0, i1 = i0 + 64;
        int g0 = 0, g1 = 0;
        if (i0 < Mz) g0 = rows[i0]; else za0 = 0;
        if (i1 < Mz) g1 = rows[i1]; else za1 = 0;
        ga0 = A + (size_t)g0 * K + kq * 8;
        ga1 = A + (size_t)g1 * K + kq * 8;
    } else {
        ga0 = A + (size_t)(m0 + r0) * K + kq * 8;
        ga1 = ga0 + (size_t)64 * K;
    }
    const __half* gb0 = Bw + (size_t)(n0 + r0) * K + kq * 8;
    const __half* gb1 = gb0 + (size_t)64 * K;

    uint32_t sa_smem = (uint32_t)__cvta_generic_to_shared(SA);
    uint32_t sb_smem = (uint32_t)__cvta_generic_to_shared(SB);
    uint32_t sa_base = sa_smem + (r0 * HKPAD + kq * 8) * 2;
    uint32_t sb_base = sb_smem + (r0 * HKPAD + kq * 8) * 2;
    const uint32_t BUFB = 128 * HKPAD * 2;
    const uint32_t HALF = 64 * HKPAD * 2;

    int NIT = K >> 5;

    auto load_tile = [&](int it) {
        uint32_t off = (uint32_t)(it % NSTAGE) * BUFB;
        cp16(sa_base + off,        ga0 + it * 32, za0);
        cp16(sa_base + off + HALF, ga1 + it * 32, za1);
        cp16(sb_base + off,        gb0 + it * 32, 16);
        cp16(sb_base + off + HALF, gb1 + it * 32, 16);
        asm volatile("cp.async.commit_group;" ::: "memory");
    };

    int warp = tid >> 5, lane = tid & 31;
    int gid = lane >> 2, tg = lane & 3;
    int wm = (warp >> 1) * 32, wn = (warp & 1) * 64;

    int a_r = lane & 15;
    int a_k = (lane & 16) ? 8 : 0;
    int b_r = (lane & 7) + ((lane & 16) ? 8 : 0);
    int b_k = (lane & 8) ? 8 : 0;

    float acc[2][8][4];
#pragma unroll
    for (int i = 0; i < 2; i++)
#pragma unroll
        for (int j = 0; j < 8; j++)
#pragma unroll
            for (int k = 0; k < 4; k++) acc[i][j][k] = 0.f;

    load_tile(0);
    if (NIT > 1) load_tile(1);
    if (NIT > 2) load_tile(2);

    for (int it = 0; it < NIT; ++it) {
        int pending = (NIT - 1 - it < 2) ? (NIT - 1 - it) : 2;
        if (pending == 2)      asm volatile("cp.async.wait_group 2;" ::: "memory");
        else if (pending == 1) asm volatile("cp.async.wait_group 1;" ::: "memory");
        else                   asm volatile("cp.async.wait_group 0;" ::: "memory");
        __syncthreads();
        if (it + 3 < NIT) load_tile(it + 3);

        uint32_t st = (uint32_t)(it % NSTAGE) * BUFB;
        uint32_t sa_st = sa_smem + st;
        uint32_t sb_st = sb_smem + st;

#pragma unroll
        for (int ks = 0; ks < 2; ks++) {
            uint32_t af[2][4], bf[8][2];
#pragma unroll
            for (int mi = 0; mi < 2; mi++)
                ldsm4(af[mi], sa_st + ((wm + mi * 16 + a_r) * HKPAD + ks * 16 + a_k) * 2);
#pragma unroll
            for (int np = 0; np < 4; np++) {
                uint32_t bq[4];
                ldsm4(bq, sb_st + ((wn + np * 16 + b_r) * HKPAD + ks * 16 + b_k) * 2);
                bf[2 * np][0] = bq[0]; bf[2 * np][1] = bq[1];
                bf[2 * np + 1][0] = bq[2]; bf[2 * np + 1][1] = bq[3];
            }
#pragma unroll
            for (int mi = 0; mi < 2; mi++)
#pragma unroll
                for (int ni = 0; ni < 8; ni++)
                    mma_f16(acc[mi][ni], af[mi], bf[ni]);
        }
    }

#pragma unroll
    for (int mi = 0; mi < 2; mi++) {
#pragma unroll
        for (int hh = 0; hh < 2; hh++) {
            int rr = m0 + wm + mi * 16 + gid + hh * 8;
            if (rr >= Mz) continue;
            const float* rrow = resid ? resid + (size_t)rr * N : nullptr;
            int tok = 0; float wgt = 0.f;
            if (OUTMODE == 3) { tok = rows[rr]; wgt = pw[rr]; }
#pragma unroll
            for (int ni = 0; ni < 8; ni++) {
                int col = n0 + wn + ni * 8 + tg * 2;
                float v0 = acc[mi][ni][hh * 2 + 0];
                float v1 = acc[mi][ni][hh * 2 + 1];
                if (bias) { v0 += bias[col]; v1 += bias[col + 1]; }
                if (GELU) {
                    v0 = 0.5f * v0 * (1.f + erff(v0 * 0.70710678118654752f));
                    v1 = 0.5f * v1 * (1.f + erff(v1 * 0.70710678118654752f));
                }
                if (rrow) { v0 += rrow[col]; v1 += rrow[col + 1]; }
                if (OUTMODE == 2) {
                    __half2* crow = (__half2*)((__half*)Cout + (size_t)z * sC + (size_t)rr * N + col);
                    *crow = __floats2half2_rn(v0, v1);
                } else if (OUTMODE == 3) {
                    float* orow = (float*)Cout + (size_t)tok * N + col;
                    atomicAdd(orow, wgt * v0);
                    atomicAdd(orow + 1, wgt * v1);
                } else {
                    float* crow = (float*)Cout + (size_t)z * sC + (size_t)rr * N + col;
                    crow[0] = v0; crow[1] = v1;
                }
            }
        }
    }
}

// ---------------- fp16 flash attention (3-stage, one sync per tile) ------------
__global__ void __launch_bounds__(256, 2)
attn_h(const __half* __restrict__ qkv, __half* __restrict__ out) {
    extern __shared__ __half sma[];
    __half* SQ = sma;                          // [128][APITCH]
    __half* SK = SQ + 128 * APITCH;            // [ASTG][64][APITCH]
    __half* SV = SK + ASTG * 64 * APITCH;      // [ASTG][64][APITCH]

    int bh = blockIdx.y;
    int b = bh / HEADS, h = bh % HEADS;
    int q0 = blockIdx.x * 128;
    int tid = threadIdx.x;
    int warp = tid >> 5, lane = tid & 31;
    int gid = lane >> 2, tg = lane & 3;
    int wm = warp * 16;

    uint32_t sq_smem = (uint32_t)__cvta_generic_to_shared(SQ);
    uint32_t sk_smem = (uint32_t)__cvta_generic_to_shared(SK);
    uint32_t sv_smem = (uint32_t)__cvta_generic_to_shared(SV);
    const uint32_t STAGE = 64 * APITCH * 2;

    int a_r = lane & 15;
    int a_k = (lane & 16) ? 8 : 0;
    int b_r = (lane & 7) + ((lane & 16) ? 8 : 0);
    int b_k = (lane & 8) ? 8 : 0;
    int v_r = (lane & 7) + ((lane & 8) ? 8 : 0);
    int v_c = (lane & 16) ? 8 : 0;

    int krow = tid >> 2, kq4 = tid & 3;
    const __half* kbase = qkv + (size_t)(b * NN + krow) * (3 * DIM) + DIM + h * HD + kq4 * 16;
    uint32_t kdst = sk_smem + (krow * APITCH + kq4 * 16) * 2;
    uint32_t vdst = sv_smem + (krow * APITCH + kq4 * 16) * 2;

    auto loadKV = [&](int kt) {
        uint32_t off = (uint32_t)(kt % ASTG) * STAGE;
        const __half* kp = kbase + (size_t)kt * 64 * 3 * DIM;
        const __half* vp = kp + DIM;
        cp16(kdst + off, kp, 16);
        cp16(kdst + off + 16, kp + 8, 16);
        cp16(vdst + off, vp, 16);
        cp16(vdst + off + 16, vp + 8, 16);
        asm volatile("cp.async.commit_group;" ::: "memory");
    };

    {
        int row = tid >> 1, cb = (tid & 1) * 32;
        const __half* qp = qkv + (size_t)(b * NN + q0 + row) * (3 * DIM) + h * HD + cb;
        __half* dst = SQ + row * APITCH + cb;
        const __half2 sc = __floats2half2_rn(0.125f, 0.125f);
#pragma unroll
        for (int j = 0; j < 4; j++) {
            __half2 v0 = *(const __half2*)(qp + j * 8 + 0);
            __half2 v1 = *(const __half2*)(qp + j * 8 + 2);
            __half2 v2 = *(const __half2*)(qp + j * 8 + 4);
            __half2 v3 = *(const __half2*)(qp + j * 8 + 6);
            *(__half2*)(dst + j * 8 + 0) = __hmul2(v0, sc);
            *(__half2*)(dst + j * 8 + 2) = __hmul2(v1, sc);
            *(__half2*)(dst + j * 8 + 4) = __hmul2(v2, sc);
            *(__half2*)(dst + j * 8 + 6) = __hmul2(v3, sc);
        }
    }
    loadKV(0);
    loadKV(1);
    __syncthreads();   // Q staged (K stage 0/1 ordering handled by wait_group)

    uint32_t qf[4][4];
#pragma unroll
    for (int s = 0; s < 4; s++)
        ldsm4(qf[s], sq_smem + ((wm + a_r) * APITCH + s * 16 + a_k) * 2);

    float of[8][4];
#pragma unroll
    for (int i = 0; i < 8; i++)
#pragma unroll
        for (int j = 0; j < 4; j++) of[i][j] = 0.f;
    float m0r = -1e30f, m1r = -1e30f, l0r = 0.f, l1r = 0.f;

    const int NT = NN / 64;
    for (int kt = 0; kt < NT; kt++) {
        int pending = (NT - 1 - kt < 1) ? 0 : 1;
        if (pending == 1) asm volatile("cp.async.wait_group 1;" ::: "memory");
        else              asm volatile("cp.async.wait_group 0;" ::: "memory");
        __syncthreads();
        if (kt + 2 < NT) loadKV(kt + 2);   // stage (kt+2)%3: last readers were iter kt-1, past sync

        uint32_t sk_st = sk_smem + (uint32_t)(kt % ASTG) * STAGE;
        uint32_t sv_st = sv_smem + (uint32_t)(kt % ASTG) * STAGE;

        float sf[8][4];
#pragma unroll
        for (int i = 0; i < 8; i++)
#pragma unroll
            for (int j = 0; j < 4; j++) sf[i][j] = 0.f;
#pragma unroll
        for (int s = 0; s < 4; s++) {
            uint32_t bf[8][2];
#pragma unroll
            for (int np = 0; np < 4; np++) {
                uint32_t bq[4];
                ldsm4(bq, sk_st + ((np * 16 + b_r) * APITCH + s * 16 + b_k) * 2);
                bf[2 * np][0] = bq[0]; bf[2 * np][1] = bq[1];
                bf[2 * np + 1][0] = bq[2]; bf[2 * np + 1][1] = bq[3];
            }
#pragma unroll
            for (int ni = 0; ni < 8; ni++)
                mma_f16(sf[ni], qf[s], bf[ni]);
        }

        float tm0 = -1e30f, tm1 = -1e30f;
#pragma unroll
        for (int ni = 0; ni < 8; ni++) {
            tm0 = fmaxf(tm0, fmaxf(sf[ni][0], sf[ni][1]));
            tm1 = fmaxf(tm1, fmaxf(sf[ni][2], sf[ni][3]));
        }
        tm0 = fmaxf(tm0, __shfl_xor_sync(0xffffffffu, tm0, 1));
        tm0 = fmaxf(tm0, __shfl_xor_sync(0xffffffffu, tm0, 2));
        tm1 = fmaxf(tm1, __shfl_xor_sync(0xffffffffu, tm1, 1));
        tm1 = fmaxf(tm1, __shfl_xor_sync(0xffffffffu, tm1, 2));
        float mn0 = fmaxf(m0r, tm0), mn1 = fmaxf(m1r, tm1);
        float c0 = __expf(m0r - mn0), c1 = __expf(m1r - mn1);
        m0r = mn0; m1r = mn1;
        float rs0 = 0.f, rs1 = 0.f;
#pragma unroll
        for (int ni = 0; ni < 8; ni++) {
            sf[ni][0] = __expf(sf[ni][0] - mn0);
            sf[ni][1] = __expf(sf[ni][1] - mn0);
            sf[ni][2] = __expf(sf[ni][2] - mn1);
            sf[ni][3] = __expf(sf[ni][3] - mn1);
            rs0 += sf[ni][0] + sf[ni][1];
            rs1 += sf[ni][2] + sf[ni][3];
        }
        rs0 += __shfl_xor_sync(0xffffffffu, rs0, 1);
        rs0 += __shfl_xor_sync(0xffffffffu, rs0, 2);
        rs1 += __shfl_xor_sync(0xffffffffu, rs1, 1);
        rs1 += __shfl_xor_sync(0xffffffffu, rs1, 2);
        l0r = l0r * c0 + rs0;
        l1r = l1r * c1 + rs1;
#pragma unroll
        for (int ni = 0; ni < 8; ni++) {
            of[ni][0] *= c0; of[ni][1] *= c0;
            of[ni][2] *= c1; of[ni][3] *= c1;
        }

#pragma unroll
        for (int s = 0; s < 4; s++) {
            uint32_t pf[4];
            pf[0] = pack2(sf[2 * s][0], sf[2 * s][1]);
            pf[1] = pack2(sf[2 * s][2], sf[2 * s][3]);
            pf[2] = pack2(sf[2 * s + 1][0], sf[2 * s + 1][1]);
            pf[3] = pack2(sf[2 * s + 1][2], sf[2 * s + 1][3]);
            uint32_t bf[8][2];
#pragma unroll
            for (int np = 0; np < 4; np++) {
                uint32_t bq[4];
                ldsm4t(bq, sv_st + ((s * 16 + v_r) * APITCH + np * 16 + v_c) * 2);
                bf[2 * np][0] = bq[0]; bf[2 * np][1] = bq[1];
                bf[2 * np + 1][0] = bq[2]; bf[2 * np + 1][1] = bq[3];
            }
#pragma unroll
            for (int ni = 0; ni < 8; ni++)
                mma_f16(of[ni], pf, bf[ni]);
        }
    }

    float i0 = 1.f / l0r, i1 = 1.f / l1r;
    __half* o0 = out + (size_t)(b * NN + q0 + wm + gid) * DIM + h * HD;
    __half* o1 = out + (size_t)(b * NN + q0 + wm + gid + 8) * DIM + h * HD;
#pragma unroll
    for (int ni = 0; ni < 8; ni++) {
        int col = ni * 8 + 2 * tg;
        *(__half2*)(o0 + col) = __floats2half2_rn(of[ni][0] * i0, of[ni][1] * i0);
        *(__half2*)(o1 + col) = __floats2half2_rn(of[ni][2] * i1, of[ni][3] * i1);
    }
}

// ------ fused LN2 + gate + fp16 h + out-init (out = x1) ------------------------
__global__ void gate_ln_kernel(const float* __restrict__ x1, const float* __restrict__ g,
                               const float* __restrict__ bparm, const float* __restrict__ gw,
                               const float* __restrict__ gb, int* __restrict__ cnt,
                               int* __restrict__ ptok, float* __restrict__ pw,
                               __half* __restrict__ hout, float* __restrict__ outinit) {
    __shared__ float xs[DIM];
    __shared__ float red[256];
    __shared__ float lg[NE];
    int t = blockIdx.x, tid = threadIdx.x;
    const float* xr = x1 + (size_t)t * DIM;
    float* orow = outinit + (size_t)t * DIM;
    float s = 0.f;
    for (int i = tid; i < DIM; i += 256) {
        float v = xr[i];
        xs[i] = v; orow[i] = v;
        s += v;
    }
    red[tid] = s; __syncthreads();
    for (int st = 128; st > 0; st >>= 1) { if (tid < st) red[tid] += red[tid + st]; __syncthreads(); }
    float mu = red[0] * (1.f / DIM);
    __syncthreads();
    s = 0.f;
    for (int i = tid; i < DIM; i += 256) { float d = xs[i] - mu; s += d * d; }
    red[tid] = s; __syncthreads();
    for (int st = 128; st > 0; st >>= 1) { if (tid < st) red[tid] += red[tid + st]; __syncthreads(); }
    float inv = rsqrtf(red[0] * (1.f / DIM) + 1e-5f);
    __syncthreads();

    int w = tid >> 5, lane = tid & 31;
    float acc = 0.f;
    const float* gr = gw + (size_t)w * DIM;
    __half* hrow = hout + (size_t)t * DIM;
    for (int k = lane; k < DIM; k += 32) {
        float hv = (xs[k] - mu) * inv * g[k] + bparm[k];
        acc += hv * gr[k];
        if (w == 0) hrow[k] = __float2half_rn(hv);
    }
#pragma unroll
    for (int off = 16; off > 0; off >>= 1) acc += __shfl_down_sync(0xffffffffu, acc, off);
    if (lane == 0) lg[w] = acc + gb[w];
    __syncthreads();
    if (tid == 0) {
        int b0 = 0; float v0 = lg[0];
        for (int e = 1; e < NE; e++) if (lg[e] > v0) { v0 = lg[e]; b0 = e; }
        int b1 = -1; float v1 = -1e30f;
        for (int e = 0; e < NE; e++) {
            if (e == b0) continue;
            if (lg[e] > v1) { v1 = lg[e]; b1 = e; }
        }
        float e1 = __expf(v1 - v0);
        float s0 = 1.f / (1.f + e1);
        float s1 = 1.f - s0;
        int p0 = atomicAdd(&cnt[b0], 1);
        int p1 = atomicAdd(&cnt[b1], 1);
        ptok[b0 * TT + p0] = t; pw[b0 * TT + p0] = s0;
        ptok[b1 * TT + p1] = t; pw[b1 * TT + p1] = s1;
    }
}

// ---------------- host launcher -------------------------------------------------
extern "C" void kernel_launch(void* const* d_in, const int* in_sizes, int n_in,
                              void* d_out, int out_size) {
    const float* x      = (const float*)d_in[0];
    const float* ln1_g  = (const float*)d_in[1];
    const float* ln1_b  = (const float*)d_in[2];
    const float* qkv_w  = (const float*)d_in[3];
    const float* proj_w = (const float*)d_in[4];
    const float* proj_b = (const float*)d_in[5];
    const float* ln2_g  = (const float*)d_in[6];
    const float* ln2_b  = (const float*)d_in[7];
    const float* gate_w = (const float*)d_in[8];
    const float* gate_b = (const float*)d_in[9];
    const float* w1     = (const float*)d_in[10];
    const float* b1     = (const float*)d_in[11];
    const float* w2     = (const float*)d_in[12];
    const float* b2     = (const float*)d_in[13];
    float* out = (float*)d_out;

    __half *h, *qkvb, *attn, *h1, *wh;
    float *x1, *pw;
    int *cnt, *ptok;
    cudaGetSymbolAddress((void**)&h, g_h);
    cudaGetSymbolAddress((void**)&qkvb, g_qkv);
    cudaGetSymbolAddress((void**)&attn, g_attn);
    cudaGetSymbolAddress((void**)&x1, g_x1);
    cudaGetSymbolAddress((void**)&h1, g_h1);
    cudaGetSymbolAddress((void**)&wh, g_wh);
    cudaGetSymbolAddress((void**)&cnt, g_cnt);
    cudaGetSymbolAddress((void**)&ptok, g_ptok);
    cudaGetSymbolAddress((void**)&pw, g_pw);

    __half* qkv_wh = wh + W_QKV_OFF;
    __half* proj_wh = wh + W_PROJ_OFF;
    __half* w1h = wh + W_W1_OFF;
    __half* w2h = wh + W_W2_OFF;

    const int GEMM_SMEM = NSTAGE * 128 * HKPAD * 2 * 2;           // 81920
    const int ATTN_SMEM = (128 + 2 * ASTG * 64) * APITCH * 2;     // 73728
    cudaFuncSetAttribute(gemm_hc<false, false, 2>, cudaFuncAttributeMaxDynamicSharedMemorySize, GEMM_SMEM);
    cudaFuncSetAttribute(gemm_hc<false, false, 0>, cudaFuncAttributeMaxDynamicSharedMemorySize, GEMM_SMEM);
    cudaFuncSetAttribute(gemm_hc<true, true, 2>,   cudaFuncAttributeMaxDynamicSharedMemorySize, GEMM_SMEM);
    cudaFuncSetAttribute(gemm_hc<false, false, 3>, cudaFuncAttributeMaxDynamicSharedMemorySize, GEMM_SMEM);
    cudaFuncSetAttribute(attn_h, cudaFuncAttributeMaxDynamicSharedMemorySize, ATTN_SMEM);

    // 0. zero counters + fused fp16 weight conversion
    zero_cnt_kernel<<<1, 32>>>(cnt);
    tohalf_all<<<4096, 256>>>((const float4*)qkv_w, (const float4*)proj_w,
                              (const float4*)w1, (const float4*)w2, (uint4*)wh);

    // 1. LN1 -> h (fp16)
    ln_kernel<<<TT, 256>>>(x, ln1_g, ln1_b, h);

    // 2. qkv = h @ qkv_w^T  (fp16 out)
    gemm_hc<false, false, 2><<<dim3(18, 32, 1), 256, GEMM_SMEM>>>(
        h, qkv_wh, nullptr, nullptr, qkvb, TT, 3 * DIM, DIM, nullptr, nullptr, nullptr, 0, 0, 0);

    // 3. attention
    attn_h<<<dim3(NN / 128, BB * HEADS), 256, ATTN_SMEM>>>(qkvb, attn);

    // 4. x1 = x + attn @ proj_w^T + proj_b  (fp32 out)  [6th launch -> ncu capture]
    gemm_hc<false, false, 0><<<dim3(6, 32, 1), 256, GEMM_SMEM>>>(
        attn, proj_wh, proj_b, x, x1, TT, DIM, DIM, nullptr, nullptr, nullptr, 0, 0, 0);

    // 5. fused LN2 + gate (+ fp16 h, + out = x1 init)
    gate_ln_kernel<<<TT, 256>>>(x1, ln2_g, ln2_b, gate_w, gate_b, cnt, ptok, pw, h, out);

    // 6. MoE up-proj + GELU (gathered, fp16 out)
    gemm_hc<true, true, 2><<<dim3(HID / 128, TT / 128, NE), 256, GEMM_SMEM>>>(
        h, w1h, b1, nullptr, h1, TT, HID, DIM, ptok, cnt, nullptr,
        0, (size_t)HID * DIM, (size_t)TT * HID);

    // 7. MoE down-proj, fused combine (scatter-atomic into out)
    gemm_hc<false, false, 3><<<dim3(6, 32, NE), 256, GEMM_SMEM>>>(
        h1, w2h, b2, nullptr, out, TT, DIM, HID, ptok, cnt, pw,
        (size_t)TT * HID, (size_t)DIM * HID, 0);
}

// round 17
// speedup vs baseline: 1.5020x; 1.5020x over previous
#include <cuda_runtime.h>
#include <cuda_fp16.h>
#include <math.h>
#include <stdint.h>

#define BB 4
#define NN 1024
#define TT 4096
#define DIM 768
#define HEADS 12
#define HD 64
#define HID 3072
#define NE 8

#define NSTAGE 3
#define HKPAD 40   // gemm smem pitch in halves (80B rows; ldmatrix conflict-free)

#define APITCH 72  // attention pitch in halves

// half weight scratch offsets (in halves)
#define W_QKV_OFF 0
#define W_QKV_N   (3 * DIM * DIM)
#define W_PROJ_OFF (W_QKV_OFF + W_QKV_N)
#define W_PROJ_N  (DIM * DIM)
#define W_W1_OFF  (W_PROJ_OFF + W_PROJ_N)
#define W_W1_N    (NE * HID * DIM)
#define W_W2_OFF  (W_W1_OFF + W_W1_N)
#define W_W2_N    (NE * DIM * HID)
#define W_TOTAL   (W_W2_OFF + W_W2_N)

// ---------------- scratch (static device globals; no allocs) ----------------
__device__ __half g_h[(size_t)TT * DIM];
__device__ __half g_qkv[(size_t)TT * 3 * DIM];
__device__ __half g_attn[(size_t)TT * DIM];
__device__ float  g_x1[(size_t)TT * DIM];
__device__ __half g_h1[(size_t)NE * TT * HID];
__device__ __half g_wh[(size_t)W_TOTAL];
__device__ int    g_cnt[NE];
__device__ int    g_ptok[NE * TT];
__device__ float  g_pw[NE * TT];     // combine weight per (expert, slot)

// ---------------- helpers ------------------------------------------------------
__device__ __forceinline__ uint32_t h2u(__half2 v) {
    union { __half2 h; uint32_t u; } cvt;
    cvt.h = v;
    return cvt.u;
}
__device__ __forceinline__ uint32_t pack2(float a, float b) {
    return h2u(__floats2half2_rn(a, b));
}

__device__ __forceinline__ void mma_f16(float* c, const uint32_t* a, const uint32_t* b) {
    asm volatile(
        "mma.sync.aligned.m16n8k16.row.col.f32.f16.f16.f32 "
        "{%0,%1,%2,%3}, {%4,%5,%6,%7}, {%8,%9}, {%0,%1,%2,%3};"
        : "+f"(c[0]), "+f"(c[1]), "+f"(c[2]), "+f"(c[3])
        : "r"(a[0]), "r"(a[1]), "r"(a[2]), "r"(a[3]), "r"(b[0]), "r"(b[1]));
}

__device__ __forceinline__ void ldsm4(uint32_t* r, uint32_t addr) {
    asm volatile("ldmatrix.sync.aligned.m8n8.x4.shared.b16 {%0,%1,%2,%3}, [%4];"
                 : "=r"(r[0]), "=r"(r[1]), "=r"(r[2]), "=r"(r[3]) : "r"(addr));
}
__device__ __forceinline__ void ldsm4t(uint32_t* r, uint32_t addr) {
    asm volatile("ldmatrix.sync.aligned.m8n8.x4.trans.shared.b16 {%0,%1,%2,%3}, [%4];"
                 : "=r"(r[0]), "=r"(r[1]), "=r"(r[2]), "=r"(r[3]) : "r"(addr));
}

__device__ __forceinline__ void cp16(uint32_t dst, const void* src, int sz) {
    asm volatile("cp.async.cg.shared.global [%0], [%1], 16, %2;"
                 :: "r"(dst), "l"(src), "r"(sz));
}

// ---------------- fused f32 -> f16 conversion of ALL weights (+ cnt zero) ------
__global__ void tohalf_all(const float4* __restrict__ qkv_w, const float4* __restrict__ proj_w,
                           const float4* __restrict__ w1, const float4* __restrict__ w2,
                           uint4* __restrict__ dst, int* __restrict__ cnt) {
    if (blockIdx.x == 0 && threadIdx.x < NE) cnt[threadIdx.x] = 0;
    const int n8 = W_TOTAL / 8;
    int i = blockIdx.x * blockDim.x + threadIdx.x;
    int stride = gridDim.x * blockDim.x;
    for (; i < n8; i += stride) {
        int e = i * 8;
        const float4* src;
        int off;
        if (e < W_PROJ_OFF)      { src = qkv_w;  off = e - W_QKV_OFF; }
        else if (e < W_W1_OFF)   { src = proj_w; off = e - W_PROJ_OFF; }
        else if (e < W_W2_OFF)   { src = w1;     off = e - W_W1_OFF; }
        else                     { src = w2;     off = e - W_W2_OFF; }
        float4 a = src[off / 4];
        float4 b = src[off / 4 + 1];
        uint4 o;
        o.x = pack2(a.x, a.y); o.y = pack2(a.z, a.w);
        o.z = pack2(b.x, b.y); o.w = pack2(b.z, b.w);
        dst[i] = o;
    }
}

// ---------------- layernorm (fp16 output) --------------------------------------
__global__ void ln_kernel(const float* __restrict__ x, const float* __restrict__ g,
                          const float* __restrict__ b, __half* __restrict__ o) {
    __shared__ float xs[DIM];
    __shared__ float red[256];
    int t = blockIdx.x, tid = threadIdx.x;
    const float* xr = x + (size_t)t * DIM;
    float s = 0.f;
    for (int i = tid; i < DIM; i += 256) { float v = xr[i]; xs[i] = v; s += v; }
    red[tid] = s; __syncthreads();
    for (int st = 128; st > 0; st >>= 1) { if (tid < st) red[tid] += red[tid + st]; __syncthreads(); }
    float mu = red[0] * (1.f / DIM);
    __syncthreads();
    s = 0.f;
    for (int i = tid; i < DIM; i += 256) { float d = xs[i] - mu; s += d * d; }
    red[tid] = s; __syncthreads();
    for (int st = 128; st > 0; st >>= 1) { if (tid < st) red[tid] += red[tid + st]; __syncthreads(); }
    float inv = rsqrtf(red[0] * (1.f / DIM) + 1e-5f);
    __half* orow = o + (size_t)t * DIM;
    for (int i = tid; i < DIM; i += 256)
        orow[i] = __float2half_rn((xs[i] - mu) * inv * g[i] + b[i]);
}

// ---------------- fp16 tensor-core GEMM (ldmatrix, BK=32, 3-stage) -------------
// OUTMODE: 0 = float, 2 = half, 3 = scatter-atomic float (MoE combine)
template <bool GATHER, bool GELU, int OUTMODE>
__global__ void __launch_bounds__(256, 2)
gemm_hc(const __half* __restrict__ A, const __half* __restrict__ Bw,
        const float* __restrict__ bias, const float* __restrict__ resid,
        void* __restrict__ Cout, int M, int N, int K,
        const int* __restrict__ rows, const int* __restrict__ cnts,
        const float* __restrict__ pw,
        size_t sA, size_t sB, size_t sC) {
    extern __shared__ __half smh[];
    __half* SA = smh;
    __half* SB = smh + (size_t)NSTAGE * 128 * HKPAD;

    int z = blockIdx.z;
    A += (size_t)z * sA; Bw += (size_t)z * sB;
    if (bias) bias += (size_t)z * N;
    if (rows) rows += (size_t)z * TT;
    if (pw)   pw += (size_t)z * TT;
    int Mz = cnts ? cnts[z] : M;
    if (Mz > M) Mz = M;
    int m0 = blockIdx.y * 128;
    if (m0 >= Mz) return;
    int n0 = blockIdx.x * 128;

    int tid = threadIdx.x;
    int r0 = tid >> 2, kq = tid & 3;

    const __half *ga0, *ga1;
    int za0 = 16, za1 = 16;
    if (GATHER) {
        int i0 = m0 + r0, i1 = i0 + 64;
        int g0 = 0, g1 = 0;
        if (i0 < Mz) g0 = rows[i0]; else za0 = 0;
        if (i1 < Mz) g1 = rows[i1]; else za1 = 0;
        ga0 = A + (size_t)g0 * K + kq * 8;
        ga1 = A + (size_t)g1 * K + kq * 8;
    } else {
        ga0 = A + (size_t)(m0 + r0) * K + kq * 8;
        ga1 = ga0 + (size_t)64 * K;
    }
    const __half* gb0 = Bw + (size_t)(n0 + r0) * K + kq * 8;
    const __half* gb1 = gb0 + (size_t)64 * K;

    uint32_t sa_smem = (uint32_t)__cvta_generic_to_shared(SA);
    uint32_t sb_smem = (uint32_t)__cvta_generic_to_shared(SB);
    uint32_t sa_base = sa_smem + (r0 * HKPAD + kq * 8) * 2;
    uint32_t sb_base = sb_smem + (r0 * HKPAD + kq * 8) * 2;
    const uint32_t BUFB = 128 * HKPAD * 2;
    const uint32_t HALF = 64 * HKPAD * 2;

    int NIT = K >> 5;

    auto load_tile = [&](int it) {
        uint32_t off = (uint32_t)(it % NSTAGE) * BUFB;
        cp16(sa_base + off,        ga0 + it * 32, za0);
        cp16(sa_base + off + HALF, ga1 + it * 32, za1);
        cp16(sb_base + off,        gb0 + it * 32, 16);
        cp16(sb_base + off + HALF, gb1 + it * 32, 16);
        asm volatile("cp.async.commit_group;" ::: "memory");
    };

    int warp = tid >> 5, lane = tid & 31;
    int gid = lane >> 2, tg = lane & 3;
    int wm = (warp >> 1) * 32, wn = (warp & 1) * 64;

    int a_r = lane & 15;
    int a_k = (lane & 16) ? 8 : 0;
    int b_r = (lane & 7) + ((lane & 16) ? 8 : 0);
    int b_k = (lane & 8) ? 8 : 0;

    float acc[2][8][4];
#pragma unroll
    for (int i = 0; i < 2; i++)
#pragma unroll
        for (int j = 0; j < 8; j++)
#pragma unroll
            for (int k = 0; k < 4; k++) acc[i][j][k] = 0.f;

    load_tile(0);
    if (NIT > 1) load_tile(1);

    for (int it = 0; it < NIT; ++it) {
        if (it + 1 < NIT) asm volatile("cp.async.wait_group 1;" ::: "memory");
        else              asm volatile("cp.async.wait_group 0;" ::: "memory");
        __syncthreads();
        if (it + 2 < NIT) load_tile(it + 2);

        uint32_t st = (uint32_t)(it % NSTAGE) * BUFB;
        uint32_t sa_st = sa_smem + st;
        uint32_t sb_st = sb_smem + st;

#pragma unroll
        for (int ks = 0; ks < 2; ks++) {
            uint32_t af[2][4], bf[8][2];
#pragma unroll
            for (int mi = 0; mi < 2; mi++)
                ldsm4(af[mi], sa_st + ((wm + mi * 16 + a_r) * HKPAD + ks * 16 + a_k) * 2);
#pragma unroll
            for (int np = 0; np < 4; np++) {
                uint32_t bq[4];
                ldsm4(bq, sb_st + ((wn + np * 16 + b_r) * HKPAD + ks * 16 + b_k) * 2);
                bf[2 * np][0] = bq[0]; bf[2 * np][1] = bq[1];
                bf[2 * np + 1][0] = bq[2]; bf[2 * np + 1][1] = bq[3];
            }
#pragma unroll
            for (int mi = 0; mi < 2; mi++)
#pragma unroll
                for (int ni = 0; ni < 8; ni++)
                    mma_f16(acc[mi][ni], af[mi], bf[ni]);
        }
    }

#pragma unroll
    for (int mi = 0; mi < 2; mi++) {
#pragma unroll
        for (int hh = 0; hh < 2; hh++) {
            int rr = m0 + wm + mi * 16 + gid + hh * 8;
            if (rr >= Mz) continue;
            const float* rrow = resid ? resid + (size_t)rr * N : nullptr;
            int tok = 0; float wgt = 0.f;
            if (OUTMODE == 3) { tok = rows[rr]; wgt = pw[rr]; }
#pragma unroll
            for (int ni = 0; ni < 8; ni++) {
                int col = n0 + wn + ni * 8 + tg * 2;
                float v0 = acc[mi][ni][hh * 2 + 0];
                float v1 = acc[mi][ni][hh * 2 + 1];
                if (bias) { v0 += bias[col]; v1 += bias[col + 1]; }
                if (GELU) {
                    v0 = 0.5f * v0 * (1.f + erff(v0 * 0.70710678118654752f));
                    v1 = 0.5f * v1 * (1.f + erff(v1 * 0.70710678118654752f));
                }
                if (rrow) { v0 += rrow[col]; v1 += rrow[col + 1]; }
                if (OUTMODE == 2) {
                    __half2* crow = (__half2*)((__half*)Cout + (size_t)z * sC + (size_t)rr * N + col);
                    *crow = __floats2half2_rn(v0, v1);
                } else if (OUTMODE == 3) {
                    float* orow = (float*)Cout + (size_t)tok * N + col;
                    atomicAdd(orow, wgt * v0);
                    atomicAdd(orow + 1, wgt * v1);
                } else {
                    float* crow = (float*)Cout + (size_t)z * sC + (size_t)rr * N + col;
                    crow[0] = v0; crow[1] = v1;
                }
            }
        }
    }
}

// ---------------- fp16 flash attention (ldmatrix + 2-stage cp.async) -----------
__global__ void __launch_bounds__(256, 2)
attn_h(const __half* __restrict__ qkv, __half* __restrict__ out) {
    extern __shared__ __half sma[];
    __half* SQ = sma;                          // [128][APITCH]
    __half* SK = SQ + 128 * APITCH;            // [2][64][APITCH]
    __half* SV = SK + 2 * 64 * APITCH;         // [2][64][APITCH]

    int bh = blockIdx.y;
    int b = bh / HEADS, h = bh % HEADS;
    int q0 = blockIdx.x * 128;
    int tid = threadIdx.x;
    int warp = tid >> 5, lane = tid & 31;
    int gid = lane >> 2, tg = lane & 3;
    int wm = warp * 16;

    uint32_t sq_smem = (uint32_t)__cvta_generic_to_shared(SQ);
    uint32_t sk_smem = (uint32_t)__cvta_generic_to_shared(SK);
    uint32_t sv_smem = (uint32_t)__cvta_generic_to_shared(SV);
    const uint32_t STAGE = 64 * APITCH * 2;

    int a_r = lane & 15;
    int a_k = (lane & 16) ? 8 : 0;
    int b_r = (lane & 7) + ((lane & 16) ? 8 : 0);
    int b_k = (lane & 8) ? 8 : 0;
    int v_r = (lane & 7) + ((lane & 8) ? 8 : 0);
    int v_c = (lane & 16) ? 8 : 0;

    int krow = tid >> 2, kq4 = tid & 3;
    const __half* kbase = qkv + (size_t)(b * NN + krow) * (3 * DIM) + DIM + h * HD + kq4 * 16;
    uint32_t kdst = sk_smem + (krow * APITCH + kq4 * 16) * 2;
    uint32_t vdst = sv_smem + (krow * APITCH + kq4 * 16) * 2;

    auto loadKV = [&](int kt) {
        uint32_t off = (uint32_t)(kt & 1) * STAGE;
        const __half* kp = kbase + (size_t)kt * 64 * 3 * DIM;
        const __half* vp = kp + DIM;
        cp16(kdst + off, kp, 16);
        cp16(kdst + off + 16, kp + 8, 16);
        cp16(vdst + off, vp, 16);
        cp16(vdst + off + 16, vp + 8, 16);
        asm volatile("cp.async.commit_group;" ::: "memory");
    };

    {
        int row = tid >> 1, cb = (tid & 1) * 32;
        const __half* qp = qkv + (size_t)(b * NN + q0 + row) * (3 * DIM) + h * HD + cb;
        __half* dst = SQ + row * APITCH + cb;
        const __half2 sc = __floats2half2_rn(0.125f, 0.125f);
#pragma unroll
        for (int j = 0; j < 4; j++) {
            __half2 v0 = *(const __half2*)(qp + j * 8 + 0);
            __half2 v1 = *(const __half2*)(qp + j * 8 + 2);
            __half2 v2 = *(const __half2*)(qp + j * 8 + 4);
            __half2 v3 = *(const __half2*)(qp + j * 8 + 6);
            *(__half2*)(dst + j * 8 + 0) = __hmul2(v0, sc);
            *(__half2*)(dst + j * 8 + 2) = __hmul2(v1, sc);
            *(__half2*)(dst + j * 8 + 4) = __hmul2(v2, sc);
            *(__half2*)(dst + j * 8 + 6) = __hmul2(v3, sc);
        }
    }
    loadKV(0);
    __syncthreads();

    uint32_t qf[4][4];
#pragma unroll
    for (int s = 0; s < 4; s++)
        ldsm4(qf[s], sq_smem + ((wm + a_r) * APITCH + s * 16 + a_k) * 2);

    float of[8][4];
#pragma unroll
    for (int i = 0; i < 8; i++)
#pragma unroll
        for (int j = 0; j < 4; j++) of[i][j] = 0.f;
    float m0r = -1e30f, m1r = -1e30f, l0r = 0.f, l1r = 0.f;

    const int NT = NN / 64;
    for (int kt = 0; kt < NT; kt++) {
        if (kt + 1 < NT) loadKV(kt + 1);
        if (kt + 1 < NT) asm volatile("cp.async.wait_group 1;" ::: "memory");
        else             asm volatile("cp.async.wait_group 0;" ::: "memory");
        __syncthreads();

        uint32_t sk_st = sk_smem + (uint32_t)(kt & 1) * STAGE;
        uint32_t sv_st = sv_smem + (uint32_t)(kt & 1) * STAGE;

        float sf[8][4];
#pragma unroll
        for (int i = 0; i < 8; i++)
#pragma unroll
            for (int j = 0; j < 4; j++) sf[i][j] = 0.f;
#pragma unroll
        for (int s = 0; s < 4; s++) {
            uint32_t bf[8][2];
#pragma unroll
            for (int np = 0; np < 4; np++) {
                uint32_t bq[4];
                ldsm4(bq, sk_st + ((np * 16 + b_r) * APITCH + s * 16 + b_k) * 2);
                bf[2 * np][0] = bq[0]; bf[2 * np][1] = bq[1];
                bf[2 * np + 1][0] = bq[2]; bf[2 * np + 1][1] = bq[3];
            }
#pragma unroll
            for (int ni = 0; ni < 8; ni++)
                mma_f16(sf[ni], qf[s], bf[ni]);
        }

        float tm0 = -1e30f, tm1 = -1e30f;
#pragma unroll
        for (int ni = 0; ni < 8; ni++) {
            tm0 = fmaxf(tm0, fmaxf(sf[ni][0], sf[ni][1]));
            tm1 = fmaxf(tm1, fmaxf(sf[ni][2], sf[ni][3]));
        }
        tm0 = fmaxf(tm0, __shfl_xor_sync(0xffffffffu, tm0, 1));
        tm0 = fmaxf(tm0, __shfl_xor_sync(0xffffffffu, tm0, 2));
        tm1 = fmaxf(tm1, __shfl_xor_sync(0xffffffffu, tm1, 1));
        tm1 = fmaxf(tm1, __shfl_xor_sync(0xffffffffu, tm1, 2));
        float mn0 = fmaxf(m0r, tm0), mn1 = fmaxf(m1r, tm1);
        float c0 = __expf(m0r - mn0), c1 = __expf(m1r - mn1);
        m0r = mn0; m1r = mn1;
        float rs0 = 0.f, rs1 = 0.f;
#pragma unroll
        for (int ni = 0; ni < 8; ni++) {
            sf[ni][0] = __expf(sf[ni][0] - mn0);
            sf[ni][1] = __expf(sf[ni][1] - mn0);
            sf[ni][2] = __expf(sf[ni][2] - mn1);
            sf[ni][3] = __expf(sf[ni][3] - mn1);
            rs0 += sf[ni][0] + sf[ni][1];
            rs1 += sf[ni][2] + sf[ni][3];
        }
        rs0 += __shfl_xor_sync(0xffffffffu, rs0, 1);
        rs0 += __shfl_xor_sync(0xffffffffu, rs0, 2);
        rs1 += __shfl_xor_sync(0xffffffffu, rs1, 1);
        rs1 += __shfl_xor_sync(0xffffffffu, rs1, 2);
        l0r = l0r * c0 + rs0;
        l1r = l1r * c1 + rs1;
#pragma unroll
        for (int ni = 0; ni < 8; ni++) {
            of[ni][0] *= c0; of[ni][1] *= c0;
            of[ni][2] *= c1; of[ni][3] *= c1;
        }

#pragma unroll
        for (int s = 0; s < 4; s++) {
            uint32_t pf[4];
            pf[0] = pack2(sf[2 * s][0], sf[2 * s][1]);
            pf[1] = pack2(sf[2 * s][2], sf[2 * s][3]);
            pf[2] = pack2(sf[2 * s + 1][0], sf[2 * s + 1][1]);
            pf[3] = pack2(sf[2 * s + 1][2], sf[2 * s + 1][3]);
            uint32_t bf[8][2];
#pragma unroll
            for (int np = 0; np < 4; np++) {
                uint32_t bq[4];
                ldsm4t(bq, sv_st + ((s * 16 + v_r) * APITCH + np * 16 + v_c) * 2);
                bf[2 * np][0] = bq[0]; bf[2 * np][1] = bq[1];
                bf[2 * np + 1][0] = bq[2]; bf[2 * np + 1][1] = bq[3];
            }
#pragma unroll
            for (int ni = 0; ni < 8; ni++)
                mma_f16(of[ni], pf, bf[ni]);
        }
        __syncthreads();
    }

    float i0 = 1.f / l0r, i1 = 1.f / l1r;
    __half* o0 = out + (size_t)(b * NN + q0 + wm + gid) * DIM + h * HD;
    __half* o1 = out + (size_t)(b * NN + q0 + wm + gid + 8) * DIM + h * HD;
#pragma unroll
    for (int ni = 0; ni < 8; ni++) {
        int col = ni * 8 + 2 * tg;
        *(__half2*)(o0 + col) = __floats2half2_rn(of[ni][0] * i0, of[ni][1] * i0);
        *(__half2*)(o1 + col) = __floats2half2_rn(of[ni][2] * i1, of[ni][3] * i1);
    }
}

// ------ fused LN2 + gate + fp16 h + out-init (out = x1) ------------------------
__global__ void gate_ln_kernel(const float* __restrict__ x1, const float* __restrict__ g,
                               const float* __restrict__ bparm, const float* __restrict__ gw,
                               const float* __restrict__ gb, int* __restrict__ cnt,
                               int* __restrict__ ptok, float* __restrict__ pw,
                               __half* __restrict__ hout, float* __restrict__ outinit) {
    __shared__ float xs[DIM];
    __shared__ float red[256];
    __shared__ float lg[NE];
    int t = blockIdx.x, tid = threadIdx.x;
    const float* xr = x1 + (size_t)t * DIM;
    float* orow = outinit + (size_t)t * DIM;
    float s = 0.f;
    for (int i = tid; i < DIM; i += 256) {
        float v = xr[i];
        xs[i] = v; orow[i] = v;
        s += v;
    }
    red[tid] = s; __syncthreads();
    for (int st = 128; st > 0; st >>= 1) { if (tid < st) red[tid] += red[tid + st]; __syncthreads(); }
    float mu = red[0] * (1.f / DIM);
    __syncthreads();
    s = 0.f;
    for (int i = tid; i < DIM; i += 256) { float d = xs[i] - mu; s += d * d; }
    red[tid] = s; __syncthreads();
    for (int st = 128; st > 0; st >>= 1) { if (tid < st) red[tid] += red[tid + st]; __syncthreads(); }
    float inv = rsqrtf(red[0] * (1.f / DIM) + 1e-5f);
    __syncthreads();

    int w = tid >> 5, lane = tid & 31;
    float acc = 0.f;
    const float* gr = gw + (size_t)w * DIM;
    __half* hrow = hout + (size_t)t * DIM;
    for (int k = lane; k < DIM; k += 32) {
        float hv = (xs[k] - mu) * inv * g[k] + bparm[k];
        acc += hv * gr[k];
        if (w == 0) hrow[k] = __float2half_rn(hv);
    }
#pragma unroll
    for (int off = 16; off > 0; off >>= 1) acc += __shfl_down_sync(0xffffffffu, acc, off);
    if (lane == 0) lg[w] = acc + gb[w];
    __syncthreads();
    if (tid == 0) {
        int b0 = 0; float v0 = lg[0];
        for (int e = 1; e < NE; e++) if (lg[e] > v0) { v0 = lg[e]; b0 = e; }
        int b1 = -1; float v1 = -1e30f;
        for (int e = 0; e < NE; e++) {
            if (e == b0) continue;
            if (lg[e] > v1) { v1 = lg[e]; b1 = e; }
        }
        float e1 = __expf(v1 - v0);
        float s0 = 1.f / (1.f + e1);
        float s1 = 1.f - s0;
        int p0 = atomicAdd(&cnt[b0], 1);
        int p1 = atomicAdd(&cnt[b1], 1);
        ptok[b0 * TT + p0] = t; pw[b0 * TT + p0] = s0;
        ptok[b1 * TT + p1] = t; pw[b1 * TT + p1] = s1;
    }
}

// ---------------- host launcher -------------------------------------------------
extern "C" void kernel_launch(void* const* d_in, const int* in_sizes, int n_in,
                              void* d_out, int out_size) {
    const float* x      = (const float*)d_in[0];
    const float* ln1_g  = (const float*)d_in[1];
    const float* ln1_b  = (const float*)d_in[2];
    const float* qkv_w  = (const float*)d_in[3];
    const float* proj_w = (const float*)d_in[4];
    const float* proj_b = (const float*)d_in[5];
    const float* ln2_g  = (const float*)d_in[6];
    const float* ln2_b  = (const float*)d_in[7];
    const float* gate_w = (const float*)d_in[8];
    const float* gate_b = (const float*)d_in[9];
    const float* w1     = (const float*)d_in[10];
    const float* b1     = (const float*)d_in[11];
    const float* w2     = (const float*)d_in[12];
    const float* b2     = (const float*)d_in[13];
    float* out = (float*)d_out;

    __half *h, *qkvb, *attn, *h1, *wh;
    float *x1, *pw;
    int *cnt, *ptok;
    cudaGetSymbolAddress((void**)&h, g_h);
    cudaGetSymbolAddress((void**)&qkvb, g_qkv);
    cudaGetSymbolAddress((void**)&attn, g_attn);
    cudaGetSymbolAddress((void**)&x1, g_x1);
    cudaGetSymbolAddress((void**)&h1, g_h1);
    cudaGetSymbolAddress((void**)&wh, g_wh);
    cudaGetSymbolAddress((void**)&cnt, g_cnt);
    cudaGetSymbolAddress((void**)&ptok, g_ptok);
    cudaGetSymbolAddress((void**)&pw, g_pw);

    __half* qkv_wh = wh + W_QKV_OFF;
    __half* proj_wh = wh + W_PROJ_OFF;
    __half* w1h = wh + W_W1_OFF;
    __half* w2h = wh + W_W2_OFF;

    const int GEMM_SMEM = NSTAGE * 128 * HKPAD * 2 * 2;           // 61440
    const int ATTN_SMEM = (128 + 4 * 64) * APITCH * 2;            // 55296
    cudaFuncSetAttribute(gemm_hc<false, false, 2>, cudaFuncAttributeMaxDynamicSharedMemorySize, GEMM_SMEM);
    cudaFuncSetAttribute(gemm_hc<false, false, 0>, cudaFuncAttributeMaxDynamicSharedMemorySize, GEMM_SMEM);
    cudaFuncSetAttribute(gemm_hc<true, true, 2>,   cudaFuncAttributeMaxDynamicSharedMemorySize, GEMM_SMEM);
    cudaFuncSetAttribute(gemm_hc<false, false, 3>, cudaFuncAttributeMaxDynamicSharedMemorySize, GEMM_SMEM);
    cudaFuncSetAttribute(attn_h, cudaFuncAttributeMaxDynamicSharedMemorySize, ATTN_SMEM);

    // 0. fused fp16 weight conversion (+ counter zeroing in block 0)
    tohalf_all<<<4096, 256>>>((const float4*)qkv_w, (const float4*)proj_w,
                              (const float4*)w1, (const float4*)w2, (uint4*)wh, cnt);

    // 1. LN1 -> h (fp16)
    ln_kernel<<<TT, 256>>>(x, ln1_g, ln1_b, h);

    // 2. qkv = h @ qkv_w^T  (fp16 out)
    gemm_hc<false, false, 2><<<dim3(18, 32, 1), 256, GEMM_SMEM>>>(
        h, qkv_wh, nullptr, nullptr, qkvb, TT, 3 * DIM, DIM, nullptr, nullptr, nullptr, 0, 0, 0);

    // 3. attention
    attn_h<<<dim3(NN / 128, BB * HEADS), 256, ATTN_SMEM>>>(qkvb, attn);

    // 4. x1 = x + attn @ proj_w^T + proj_b  (fp32 out)
    gemm_hc<false, false, 0><<<dim3(6, 32, 1), 256, GEMM_SMEM>>>(
        attn, proj_wh, proj_b, x, x1, TT, DIM, DIM, nullptr, nullptr, nullptr, 0, 0, 0);

    // 5. fused LN2 + gate (+ fp16 h, + out = x1 init)
    gate_ln_kernel<<<TT, 256>>>(x1, ln2_g, ln2_b, gate_w, gate_b, cnt, ptok, pw, h, out);

    // 6. MoE up-proj + GELU (gathered, fp16 out)
    gemm_hc<true, true, 2><<<dim3(HID / 128, TT / 128, NE), 256, GEMM_SMEM>>>(
        h, w1h, b1, nullptr, h1, TT, HID, DIM, ptok, cnt, nullptr,
        0, (size_t)HID * DIM, (size_t)TT * HID);

    // 7. MoE down-proj, fused combine (scatter-atomic into out)
    gemm_hc<false, false, 3><<<dim3(6, 32, NE), 256, GEMM_SMEM>>>(
        h1, w2h, b2, nullptr, out, TT, DIM, HID, ptok, cnt, pw,
        (size_t)TT * HID, (size_t)DIM * HID, 0);
}